// round 1
// baseline (speedup 1.0000x reference)
#include <cuda_runtime.h>

#define GX 512
#define GY 512
#define MAXP 32
#define CELLS (GX * GY)          // 262144 pillars per batch
#define MAXB 4
#define MAXG (MAXB * CELLS)      // scratch sized for up to 4 batches
#define SCAN_BLK 1024            // elements per scan block

// ---- scratch (device globals: no allocations allowed) ----
__device__ __align__(16) int g_counts[MAXG];
__device__ __align__(16) int g_lastpos[MAXG];
__device__ __align__(16) int g_winrank[MAXG];
__device__ int g_partials[MAXG / SCAN_BLK];
__device__ int g_offsets[MAXG / SCAN_BLK];

// flat pillar index, bit-exact vs reference: float32 IEEE divide by 0.2f,
// truncate toward zero (points are non-negative), clip to [0, 511]
__device__ __forceinline__ int flat_of(float x, float y, int b) {
    float fx = __fdiv_rn(x, 0.2f);
    float fy = __fdiv_rn(y, 0.2f);
    int ix = (int)fx;
    int iy = (int)fy;
    ix = min(max(ix, 0), GX - 1);
    iy = min(max(iy, 0), GY - 1);
    return b * CELLS + ix * GY + iy;
}

__global__ void k_init(int g4) {
    int i = blockIdx.x * blockDim.x + threadIdx.x;
    if (i < g4) {
        ((int4*)g_counts)[i]  = make_int4(0, 0, 0, 0);
        int4 m = make_int4(-1, -1, -1, -1);
        ((int4*)g_lastpos)[i] = m;
        ((int4*)g_winrank)[i] = m;
    }
}

__global__ void k_count(const float4* __restrict__ pts,
                        const int* __restrict__ bidx, int N) {
    int i = blockIdx.x * blockDim.x + threadIdx.x;
    if (i < N) {
        float4 p = pts[i];
        atomicAdd(&g_counts[flat_of(p.x, p.y, bidx[i])], 1);
    }
}

__global__ void k_lastpos(const float4* __restrict__ pts,
                          const int* __restrict__ bidx, int N) {
    int i = blockIdx.x * blockDim.x + threadIdx.x;
    if (i < N) {
        float4 p = pts[i];
        int f = flat_of(p.x, p.y, bidx[i]);
        if (g_counts[f] <= MAXP)            // drop ALL points of over-full pillars
            atomicMax(&g_lastpos[f], i);    // last-write-wins == max point index
    }
}

// pass A: per-block (1024 pillars) occupied-count
__global__ void k_partials() {
    int base = blockIdx.x * SCAN_BLK + threadIdx.x * 4;
    int4 c = *(const int4*)&g_counts[base];
    int cnt = (c.x > 0) + (c.y > 0) + (c.z > 0) + (c.w > 0);
    __shared__ int sh[8];
    #pragma unroll
    for (int o = 16; o > 0; o >>= 1) cnt += __shfl_down_sync(0xffffffffu, cnt, o);
    if ((threadIdx.x & 31) == 0) sh[threadIdx.x >> 5] = cnt;
    __syncthreads();
    if (threadIdx.x < 8) {
        int v = sh[threadIdx.x];
        #pragma unroll
        for (int o = 4; o > 0; o >>= 1) v += __shfl_down_sync(0xffu, v, o);
        if (threadIdx.x == 0) g_partials[blockIdx.x] = v;
    }
}

// pass B: single-block exclusive scan of block partials (nb <= 1024)
__global__ void k_scan(int nb) {
    __shared__ int sh[1024];
    int t = threadIdx.x;
    int v = (t < nb) ? g_partials[t] : 0;
    sh[t] = v;
    __syncthreads();
    for (int o = 1; o < 1024; o <<= 1) {
        int add = (t >= o) ? sh[t - o] : 0;
        __syncthreads();
        sh[t] += add;
        __syncthreads();
    }
    if (t < nb) g_offsets[t] = sh[t] - v;   // exclusive prefix
}

// pass C: winrank[rank] = lastpos[pillar] for each occupied pillar, in order
__global__ void k_place() {
    int base = blockIdx.x * SCAN_BLK + threadIdx.x * 4;
    int4 c = *(const int4*)&g_counts[base];
    int o0 = c.x > 0, o1 = c.y > 0, o2 = c.z > 0, o3 = c.w > 0;
    int cnt = o0 + o1 + o2 + o3;
    int lane = threadIdx.x & 31, w = threadIdx.x >> 5;
    int inc = cnt;
    #pragma unroll
    for (int o = 1; o < 32; o <<= 1) {
        int v = __shfl_up_sync(0xffffffffu, inc, o);
        if (lane >= o) inc += v;
    }
    __shared__ int ws[8];
    if (lane == 31) ws[w] = inc;
    __syncthreads();
    int woff = 0;
    for (int k = 0; k < w; k++) woff += ws[k];
    int r = g_offsets[blockIdx.x] + woff + (inc - cnt);
    if (o0) g_winrank[r++] = g_lastpos[base + 0];
    if (o1) g_winrank[r++] = g_lastpos[base + 1];
    if (o2) g_winrank[r++] = g_lastpos[base + 2];
    if (o3) g_winrank[r++] = g_lastpos[base + 3];
}

// one warp per output pillar slot: lane p writes the (p,:) float4 (streaming)
__global__ void k_fill(const float4* __restrict__ pts, float4* __restrict__ out, int G) {
    int tid  = blockIdx.x * blockDim.x + threadIdx.x;
    int warp = tid >> 5;
    int lane = tid & 31;
    if (warp >= G) return;
    int idx = g_winrank[warp];                    // broadcast load (same addr per warp)
    float4 v = make_float4(0.f, 0.f, 0.f, 0.f);
    if (idx >= 0) v = __ldg(&pts[idx]);           // winner point, broadcast
    __stcs(&out[(size_t)warp * 32 + lane], v);    // 512B coalesced per warp, streaming
}

// zero voxel_counts tail (G int32 zeros)
__global__ void k_ztail(float4* __restrict__ t, int n4) {
    int i = blockIdx.x * blockDim.x + threadIdx.x;
    if (i < n4) __stcs(&t[i], make_float4(0.f, 0.f, 0.f, 0.f));
}

extern "C" void kernel_launch(void* const* d_in, const int* in_sizes, int n_in,
                              void* d_out, int out_size) {
    const float4* pts = (const float4*)d_in[0];
    const int* bidx   = (const int*)d_in[1];
    int N = in_sizes[0] / 4;                     // all_points is [N,4] float32
    // out = B*GX*GY*(P*C) features + B*GX*GY counts = B*CELLS*129 elements
    int B = out_size / (CELLS * (MAXP * 4 + 1));
    if (B < 1) B = 1;
    if (B > MAXB) B = MAXB;
    int G  = B * CELLS;
    int nb = G / SCAN_BLK;                       // scan blocks (512 for B=2)

    float4* outf = (float4*)d_out;
    // counts region starts after G*32 float4 feature rows
    float4* tail = (float4*)((float*)d_out + (size_t)G * MAXP * 4);

    k_init<<<(G / 4 + 255) / 256, 256>>>(G / 4);
    k_count<<<(N + 255) / 256, 256>>>(pts, bidx, N);
    k_lastpos<<<(N + 255) / 256, 256>>>(pts, bidx, N);
    k_partials<<<nb, 256>>>();
    k_scan<<<1, 1024>>>(nb);
    k_place<<<nb, 256>>>();
    k_fill<<<(G * 32) / 256, 256>>>(pts, outf, G);
    k_ztail<<<(G / 4 + 255) / 256, 256>>>(tail, G / 4);
}

// round 2
// speedup vs baseline: 1.0985x; 1.0985x over previous
#include <cuda_runtime.h>

#define GX 512
#define GY 512
#define MAXP 32
#define CELLS (GX * GY)          // 262144 pillars per batch
#define MAXB 4
#define MAXG (MAXB * CELLS)
#define SCAN_BLK 1024            // pillars per scan tile
#define NTILES (MAXG / SCAN_BLK)

// ---- scratch (zero-initialized device globals; no allocations allowed) ----
// g_counts: per-pillar point count (reset to 0 by k_scanplace each call)
// g_lastpos: per-pillar max point index + 1; 0 = none (reset each call)
// g_winrank: rank -> winner point index + 1; 0 = empty (ranks >= M never written, stay 0)
__device__ __align__(16) int g_counts[MAXG];
__device__ __align__(16) int g_lastpos[MAXG];
__device__ __align__(16) int g_winrank[MAXG];
__device__ unsigned g_tile[NTILES];   // decoupled-lookback state: [31:30]=status, [29:0]=value

// flat pillar index, bit-exact vs reference: float32 IEEE divide by 0.2f,
// truncate toward zero (points are non-negative), clip to [0, 511]
__device__ __forceinline__ int flat_of(float x, float y, int b) {
    int ix = (int)__fdiv_rn(x, 0.2f);
    int iy = (int)__fdiv_rn(y, 0.2f);
    ix = min(max(ix, 0), GX - 1);
    iy = min(max(iy, 0), GY - 1);
    return b * CELLS + ix * GY + iy;
}

// One pass over points: count + last-write-wins winner (unconditional; the
// count<=32 mask is applied at place time). Also resets this call's lookback
// tile states (stream order guarantees this precedes k_scanplace).
__global__ void k_points(const float4* __restrict__ pts,
                         const int* __restrict__ bidx, int N, int nb) {
    int i = blockIdx.x * blockDim.x + threadIdx.x;
    if (i < nb) g_tile[i] = 0u;
    if (i < N) {
        float4 p = pts[i];
        int f = flat_of(p.x, p.y, bidx[i]);
        atomicAdd(&g_counts[f], 1);
        atomicMax(&g_lastpos[f], i + 1);   // idx+1; max == last masked write
    }
}

// Single-pass scan over pillars: rank occupied pillars in order (decoupled
// lookback), write g_winrank[rank] = winner (or 0 if pillar overfull), and
// reset g_counts/g_lastpos for the next graph replay.
__global__ void __launch_bounds__(256) k_scanplace() {
    const int b = blockIdx.x, t = threadIdx.x;
    const int lane = t & 31, w = t >> 5;
    const int base = b * SCAN_BLK + t * 4;

    int4 c  = *(const int4*)&g_counts[base];
    int4 lp = *(const int4*)&g_lastpos[base];
    *(int4*)&g_counts[base]  = make_int4(0, 0, 0, 0);   // reset for next call
    *(int4*)&g_lastpos[base] = make_int4(0, 0, 0, 0);

    int o0 = c.x > 0, o1 = c.y > 0, o2 = c.z > 0, o3 = c.w > 0;
    int cnt = o0 + o1 + o2 + o3;

    // warp-level inclusive scan of cnt
    int inc = cnt;
    #pragma unroll
    for (int o = 1; o < 32; o <<= 1) {
        int v = __shfl_up_sync(0xffffffffu, inc, o);
        if (lane >= o) inc += v;
    }
    __shared__ int ws[8];        // per-warp totals
    __shared__ int woff[8];      // per-warp exclusive offsets
    __shared__ int sh_excl;      // this tile's exclusive prefix
    if (lane == 31) ws[w] = inc;
    __syncthreads();

    if (w == 0) {
        // scan the 8 warp totals
        int v = (lane < 8) ? ws[lane] : 0;
        #pragma unroll
        for (int o = 1; o < 8; o <<= 1) {
            int u = __shfl_up_sync(0xffffffffu, v, o);
            if (lane >= o) v += u;
        }
        if (lane < 8) woff[lane] = v - ws[lane];
        int agg = __shfl_sync(0xffffffffu, v, 7);

        // publish aggregate (tile 0 publishes inclusive directly)
        if (lane == 0) {
            unsigned pub = ((b == 0 ? 2u : 1u) << 30) | (unsigned)agg;
            atomicExch(&g_tile[b], pub);
        }
        // warp-parallel lookback
        int excl = 0;
        if (b > 0) {
            int j = b - 1;
            while (true) {
                int jj = j - lane;
                unsigned v2;
                if (jj >= 0) {
                    volatile unsigned* p = &g_tile[jj];
                    do { v2 = *p; } while (!(v2 >> 30));
                } else {
                    v2 = 2u << 30;   // virtual prefix 0 before tile 0
                }
                unsigned ball = __ballot_sync(0xffffffffu, (v2 >> 30) == 2u);
                int fl = __ffs(ball) - 1;   // closest tile with full prefix
                unsigned contrib = ball ? ((lane <= fl) ? (v2 & 0x3fffffffu) : 0u)
                                        : (v2 & 0x3fffffffu);
                #pragma unroll
                for (int o = 16; o > 0; o >>= 1)
                    contrib += __shfl_down_sync(0xffffffffu, contrib, o);
                if (lane == 0) excl += (int)contrib;
                if (ball) break;
                j -= 32;
            }
            if (lane == 0)
                atomicExch(&g_tile[b], (2u << 30) | (unsigned)(excl + agg));
        }
        if (lane == 0) sh_excl = excl;
    }
    __syncthreads();

    int r = sh_excl + woff[w] + (inc - cnt);
    if (o0) g_winrank[r++] = (c.x <= MAXP) ? lp.x : 0;
    if (o1) g_winrank[r++] = (c.y <= MAXP) ? lp.y : 0;
    if (o2) g_winrank[r++] = (c.z <= MAXP) ? lp.z : 0;
    if (o3) g_winrank[r]   = (c.w <= MAXP) ? lp.w : 0;
}

// One warp per output pillar slot: lane p streams one float4 (512B/warp,
// fully coalesced). Tail threads zero the voxel_counts region.
__global__ void __launch_bounds__(256) k_fill(const float4* __restrict__ pts,
                                              float4* __restrict__ out, int G) {
    int tid = blockIdx.x * blockDim.x + threadIdx.x;
    int nfeat = G * 32;                         // float4 elements in feature region
    if (tid < nfeat) {
        int idx = g_winrank[tid >> 5];          // broadcast load per warp
        float4 v = make_float4(0.f, 0.f, 0.f, 0.f);
        if (idx > 0) v = __ldg(&pts[idx - 1]);
        __stcs(&out[tid], v);
    } else {
        int j = tid - nfeat;
        if (j < G / 4)
            __stcs(&out[nfeat + j], make_float4(0.f, 0.f, 0.f, 0.f));
    }
}

extern "C" void kernel_launch(void* const* d_in, const int* in_sizes, int n_in,
                              void* d_out, int out_size) {
    const float4* pts = (const float4*)d_in[0];
    const int* bidx   = (const int*)d_in[1];
    int N = in_sizes[0] / 4;                    // all_points is [N,4] float32
    int B = out_size / (CELLS * (MAXP * 4 + 1));
    if (B < 1) B = 1;
    if (B > MAXB) B = MAXB;
    int G  = B * CELLS;
    int nb = G / SCAN_BLK;

    k_points<<<(N + 255) / 256, 256>>>(pts, bidx, N, nb);
    k_scanplace<<<nb, 256>>>();
    int total = G * 32 + G / 4;
    k_fill<<<(total + 255) / 256, 256>>>(pts, (float4*)d_out, G);
}